// round 12
// baseline (speedup 1.0000x reference)
#include <cuda_runtime.h>
#include <math.h>
#include <stdint.h>

#define N_RNA 4096
#define N_ATAC 8192
#define IN_C 256
#define HID 128
#define THR_S 0.8f

// ---------------- scratch (static device memory; no allocations) ----------------
__device__ float g_Q[N_RNA * HID];
__device__ float g_K[N_ATAC * HID];
__device__ float g_KT[HID * N_ATAC];          // K transposed: [d 128][a 8192]
__device__ float g_VR[N_RNA * HID];
__device__ float g_VA[N_ATAC * HID];
__device__ float g_AGGR[N_RNA * HID];
__device__ float g_AGGA[N_ATAC * HID];
__device__ float g_CR[N_RNA * 2 * HID];
__device__ float g_CA[N_ATAC * 2 * HID];
__device__ float g_L[2u * N_RNA * N_ATAC];    // masked logits [h][r][a]  (268 MB)
__device__ float g_LM[2u * N_RNA * (N_ATAC / 4)];   // group-of-4 maxes (67 MB)
__device__ float g_LM2[2u * N_RNA * (N_ATAC / 32)]; // max-over-32 groups (8.4 MB)
__device__ float g_W[2 * N_RNA * 10];         // top-k weights per (h,r)
__device__ int g_WI[2 * N_RNA * 10];          // top-k indices per (h,r)

// ---------------- batched GEMM (unchanged, known-good) ----------------
struct GemmOp {
    const float* A;
    const float* W;
    const float* B;
    float* C;
    int M;
    int K;
    int ldc;
    int coff;
};
struct GemmBatch { GemmOp op[6]; };

__global__ void __launch_bounds__(256) gemm_kernel(GemmBatch batch) {
    const GemmOp op = batch.op[blockIdx.y];
    const int m0 = blockIdx.x * 64;
    if (m0 >= op.M) return;

    __shared__ float a_s[64][33];
    __shared__ float w_s[32][128];

    float acc[8][4];
#pragma unroll
    for (int i = 0; i < 8; ++i) {
        acc[i][0] = 0.f; acc[i][1] = 0.f; acc[i][2] = 0.f; acc[i][3] = 0.f;
    }

    const int t = threadIdx.x;
    const float4* A4 = (const float4*)op.A;
    const float4* W4 = (const float4*)op.W;
    const int Kd4 = op.K >> 2;

    for (int kk = 0; kk < op.K; kk += 32) {
        __syncthreads();
        {
            int k4 = t & 7, r = t >> 3;
#pragma unroll
            for (int rr = 0; rr < 2; ++rr) {
                float4 v = A4[(size_t)(m0 + r + rr * 32) * Kd4 + (kk >> 2) + k4];
                a_s[r + rr * 32][k4 * 4 + 0] = v.x;
                a_s[r + rr * 32][k4 * 4 + 1] = v.y;
                a_s[r + rr * 32][k4 * 4 + 2] = v.z;
                a_s[r + rr * 32][k4 * 4 + 3] = v.w;
            }
        }
        {
#pragma unroll
            for (int p = 0; p < 4; ++p) {
                int idx = t + p * 256;
                int k = idx >> 5, c4 = idx & 31;
                *(float4*)&w_s[k][c4 * 4] = W4[(size_t)(kk + k) * 32 + c4];
            }
        }
        __syncthreads();
#pragma unroll
        for (int k = 0; k < 32; ++k) {
            float4 w4 = *(const float4*)&w_s[k][(t & 31) * 4];
#pragma unroll
            for (int i = 0; i < 8; ++i) {
                float av = a_s[(t >> 5) * 8 + i][k];
                acc[i][0] += av * w4.x;
                acc[i][1] += av * w4.y;
                acc[i][2] += av * w4.z;
                acc[i][3] += av * w4.w;
            }
        }
    }

    const int c = (t & 31) * 4;
    const int rb = (t >> 5) * 8;
    float4 b4 = *(const float4*)&op.B[c];
#pragma unroll
    for (int i = 0; i < 8; ++i) {
        size_t row = (size_t)(m0 + rb + i);
        float4 o;
        o.x = acc[i][0] + b4.x;
        o.y = acc[i][1] + b4.y;
        o.z = acc[i][2] + b4.z;
        o.w = acc[i][3] + b4.w;
        *(float4*)&op.C[row * op.ldc + op.coff + c] = o;
    }
}

// ---------------- K transpose: g_K[a][d] -> g_KT[d][a] ----------------
__global__ void __launch_bounds__(256) transpose_k() {
    __shared__ float ts[64][133];
    const int t = threadIdx.x;
    const int a0 = blockIdx.x * 64;
    const float4* K4 = (const float4*)g_K;
#pragma unroll
    for (int j = 0; j < 8; ++j) {
        int idx = t + 256 * j;
        int r = idx >> 5, c4 = idx & 31;
        float4 v = K4[(size_t)(a0 + r) * 32 + c4];
        ts[r][c4 * 4 + 0] = v.x;
        ts[r][c4 * 4 + 1] = v.y;
        ts[r][c4 * 4 + 2] = v.z;
        ts[r][c4 * 4 + 3] = v.w;
    }
    __syncthreads();
    float4* KT4 = (float4*)g_KT;
#pragma unroll
    for (int j = 0; j < 8; ++j) {
        int idx = t + 256 * j;
        int d = idx >> 4, ac4 = idx & 15;
        float4 o;
        o.x = ts[ac4 * 4 + 0][d];
        o.y = ts[ac4 * 4 + 1][d];
        o.z = ts[ac4 * 4 + 2][d];
        o.w = ts[ac4 * 4 + 3][d];
        KT4[((size_t)d * N_ATAC + a0) / 4 + ac4] = o;
    }
}

// ---------------- logits GEMM (EXACT round-10 version; reg-safe) ----------------
__global__ void __launch_bounds__(256, 2) logits_kernel(const float* __restrict__ mask) {
    extern __shared__ float sm[];
    float* const a_f = sm;                          // [128][68] floats
    float4* const b4_s = (float4*)(sm + 128 * 68);  // [64][33] float4

    const int t = threadIdx.x;
    const int n0 = blockIdx.x * 128;
    const int m0 = blockIdx.y * 128;
    const int h = blockIdx.z;

    {
        const float4* Q4 = (const float4*)g_Q;
        float4* a4 = (float4*)a_f;
        const int k4 = t & 15, mq = t >> 4;
#pragma unroll
        for (int j = 0; j < 8; ++j) {
            int mm = mq + 16 * j;
            a4[mm * 17 + k4] = Q4[(size_t)(m0 + mm) * 32 + h * 16 + k4];
        }
    }
    {
        const float4* KT4 = (const float4*)g_KT;
        const int gq = t & 31, k2 = t >> 5;
#pragma unroll
        for (int j = 0; j < 8; ++j) {
            int k = k2 + 8 * j;
            b4_s[k * 33 + gq] =
                KT4[((size_t)(h * 64 + k) * N_ATAC + n0) / 4 + gq];
        }
    }
    __syncthreads();

    const int tx = t & 31;
    const int ty = t >> 5;

    float acc[16][4];
#pragma unroll
    for (int i = 0; i < 16; ++i) {
        acc[i][0] = 0.f; acc[i][1] = 0.f; acc[i][2] = 0.f; acc[i][3] = 0.f;
    }

    const float* arow = a_f + ty * 16 * 68;

#pragma unroll 4
    for (int k = 0; k < 64; ++k) {
        float4 b = b4_s[k * 33 + tx];
#pragma unroll
        for (int i = 0; i < 16; ++i) {
            float av = arow[i * 68 + k];
            acc[i][0] += av * b.x;
            acc[i][1] += av * b.y;
            acc[i][2] += av * b.z;
            acc[i][3] += av * b.w;
        }
    }

    const float4* M4 = (const float4*)mask;
    float4* L4 = (float4*)g_L;
#pragma unroll
    for (int i = 0; i < 16; ++i) {
        const int r = m0 + ty * 16 + i;
        float4 mv = M4[(size_t)r * (N_ATAC / 4) + (n0 >> 2) + tx];
        float4 o;
        o.x = acc[i][0] * mv.x;
        o.y = acc[i][1] * mv.y;
        o.z = acc[i][2] * mv.z;
        o.w = acc[i][3] * mv.w;
        L4[((size_t)h * N_RNA + r) * (N_ATAC / 4) + (n0 >> 2) + tx] = o;
        // group-of-4 max for the scan pre-filter (coalesced 4B store per lane)
        g_LM[((size_t)h * N_RNA + r) * (N_ATAC / 4) + (n0 >> 2) + tx] =
            fmaxf(fmaxf(o.x, o.y), fmaxf(o.z, o.w));
    }
}

// ---------------- reduce: LM (group-of-4 maxes) -> LM2 (max-over-32) ----------------
// Thread i: LM2[i] = max of LM[8i .. 8i+7]  (two float4 loads, one float store)
__global__ void __launch_bounds__(256) reduce_lm() {
    const int i = blockIdx.x * 256 + threadIdx.x;
    const float4* LM4 = (const float4*)g_LM;
    float4 a = LM4[(size_t)i * 2];
    float4 b = LM4[(size_t)i * 2 + 1];
    float m = fmaxf(fmaxf(fmaxf(a.x, a.y), fmaxf(a.z, a.w)),
                    fmaxf(fmaxf(b.x, b.y), fmaxf(b.z, b.w)));
    g_LM2[i] = m;
}

// ---------------- top-k helpers ----------------
__device__ __forceinline__ bool tk_better(float v, int i, float v2, int i2) {
    return (v > v2) || (v == v2 && i < i2);
}

__device__ __forceinline__ void tk_insert(float* bv, int* bi, float v, int gi) {
    bool done = false;
#pragma unroll
    for (int k = 9; k > 0; --k) {
        if (!done) {
            if (tk_better(v, gi, bv[k - 1], bi[k - 1])) {
                bv[k] = bv[k - 1];
                bi[k] = bi[k - 1];
            } else {
                bv[k] = v;
                bi[k] = gi;
                done = true;
            }
        }
    }
    if (!done) { bv[0] = v; bi[0] = gi; }
}

__device__ __forceinline__ float warp_max(float v) {
#pragma unroll
    for (int off = 16; off; off >>= 1)
        v = fmaxf(v, __shfl_xor_sync(0xffffffffu, v, off));
    return v;
}

// ---------------- scan kernel v3 (EXACT round-11 version; verified correct) ----------------
__global__ void __launch_bounds__(256) scan_kernel() {
    __shared__ float tvs[8][32][10];
    __shared__ int tis[8][32][10];

    const int t = threadIdx.x;
    const int w = t >> 5;
    const int lane = t & 31;
    const int ridx = blockIdx.x * 8 + w;           // h*4096 + r

    const float4* LM4 = (const float4*)g_LM2;
    const float4* L4 = (const float4*)g_L;
    const size_t mbase = (size_t)ridx * (N_ATAC / 128);  // 64 float4 of group maxes
    const size_t lbase = (size_t)ridx * (N_ATAC / 4);    // 2048 float4 of logits

    float4 u0 = LM4[mbase + lane];
    float4 u1 = LM4[mbase + 32 + lane];
    float gm[8] = {u0.x, u0.y, u0.z, u0.w, u1.x, u1.y, u1.z, u1.w};

    float lmax = -1e30f;
#pragma unroll
    for (int g = 0; g < 8; ++g) lmax = fmaxf(lmax, gm[g]);

    // warp-select 10th largest of the 32 lane maxes -> safe thr
    float x = lmax;
    float thr = -1e30f;
#pragma unroll
    for (int k = 0; k < 10; ++k) {
        float m = warp_max(x);
        thr = m;
        unsigned b = __ballot_sync(0xffffffffu, x == m);
        int src = __ffs(b) - 1;
        if (lane == src) x = -1e30f;
    }

    float bv[10];
    int bi[10];
#pragma unroll
    for (int k = 0; k < 10; ++k) { bv[k] = -1e30f; bi[k] = 0x7fffffff; }

#pragma unroll
    for (int half = 0; half < 2; ++half) {
#pragma unroll
        for (int gg = 0; gg < 4; ++gg) {
            if (gm[half * 4 + gg] >= fmaxf(thr, bv[9])) {
                const int grp = half * 128 + lane * 4 + gg;   // group of 32 elements
                const float4* lp = L4 + lbase + (size_t)grp * 8;
                const int abase = grp * 32;
#pragma unroll
                for (int q = 0; q < 8; ++q) {
                    float4 lv = lp[q];
                    float mx4 = fmaxf(fmaxf(lv.x, lv.y), fmaxf(lv.z, lv.w));
                    if (mx4 >= fmaxf(thr, bv[9])) {
                        const int a0 = abase + q * 4;
                        if (tk_better(lv.x, a0, bv[9], bi[9])) tk_insert(bv, bi, lv.x, a0);
                        if (tk_better(lv.y, a0 + 1, bv[9], bi[9])) tk_insert(bv, bi, lv.y, a0 + 1);
                        if (tk_better(lv.z, a0 + 2, bv[9], bi[9])) tk_insert(bv, bi, lv.z, a0 + 2);
                        if (tk_better(lv.w, a0 + 3, bv[9], bi[9])) tk_insert(bv, bi, lv.w, a0 + 3);
                    }
                }
            }
        }
        if (half == 0) thr = fmaxf(thr, warp_max(bv[9]));
    }

#pragma unroll
    for (int k = 0; k < 10; ++k) { tvs[w][lane][k] = bv[k]; tis[w][lane][k] = bi[k]; }
    __syncwarp();

    if (lane < 8) {
        float fv[10];
        int fi[10];
#pragma unroll
        for (int k = 0; k < 10; ++k) { fv[k] = -1e30f; fi[k] = 0x7fffffff; }
        for (int s = 0; s < 4; ++s)
            for (int k = 0; k < 10; ++k) {
                float v = tvs[w][lane * 4 + s][k];
                int gi = tis[w][lane * 4 + s][k];
                if (tk_better(v, gi, fv[9], fi[9])) tk_insert(fv, fi, v, gi);
            }
#pragma unroll
        for (int k = 0; k < 10; ++k) { tvs[w][lane][k] = fv[k]; tis[w][lane][k] = fi[k]; }
    }
    __syncwarp();

    if (lane == 0) {
        float fv[10];
        int fi[10];
#pragma unroll
        for (int k = 0; k < 10; ++k) { fv[k] = -1e30f; fi[k] = 0x7fffffff; }
        for (int s = 0; s < 8; ++s)
            for (int k = 0; k < 10; ++k) {
                float v = tvs[w][s][k];
                int gi = tis[w][s][k];
                if (tk_better(v, gi, fv[9], fi[9])) tk_insert(fv, fi, v, gi);
            }
        float sig[10];
#pragma unroll
        for (int k = 0; k < 10; ++k) sig[k] = 1.f / (1.f + expf(-fv[k]));
        float e[10];
        float den = 0.f;
#pragma unroll
        for (int k = 0; k < 10; ++k) { e[k] = expf(sig[k] - sig[0]); den += e[k]; }
        float inv = 1.f / den;
#pragma unroll
        for (int k = 0; k < 10; ++k) {
            float ww = e[k] * inv;
            if (!(sig[k] > THR_S)) ww = 0.f;
            g_W[ridx * 10 + k] = ww;
            g_WI[ridx * 10 + k] = fi[k];
        }
    }
}

// ---------------- aggregation kernel: sparse gather + scatter ----------------
__global__ void __launch_bounds__(256) agg_kernel() {
    const int t = threadIdx.x;
    const int d = t & 63;
    const int q = t >> 6;
    const int ridx = blockIdx.x * 4 + q;
    const int h = ridx >> 12;
    const int r = ridx & 4095;

    float wv[10];
    int wi[10];
#pragma unroll
    for (int k = 0; k < 10; ++k) { wv[k] = g_W[ridx * 10 + k]; wi[k] = g_WI[ridx * 10 + k]; }

    const float vr = g_VR[(size_t)r * 128 + h * 64 + d];
    float accO = 0.f;
#pragma unroll
    for (int k = 0; k < 10; ++k) {
        float w = wv[k];
        int a = wi[k];
        if (w != 0.f) {
            accO += w * g_VA[(size_t)a * 128 + h * 64 + d];
            atomicAdd(&g_AGGA[(size_t)a * 128 + h * 64 + d], w * vr);
        }
    }
    g_AGGR[(size_t)r * 128 + h * 64 + d] = accO;
}

// ---------------- launch ----------------
extern "C" void kernel_launch(void* const* d_in, const int* in_sizes, int n_in,
                              void* d_out, int out_size) {
    const float* x_rna = (const float*)d_in[0];
    const float* x_atac = (const float*)d_in[1];
    const float* chrom_mask = (const float*)d_in[2];
    const float* Wq = (const float*)d_in[3];
    const float* bq = (const float*)d_in[4];
    const float* Wk = (const float*)d_in[5];
    const float* bk = (const float*)d_in[6];
    const float* Wvr = (const float*)d_in[7];
    const float* bvr = (const float*)d_in[8];
    const float* Wva = (const float*)d_in[9];
    const float* bva = (const float*)d_in[10];
    const float* Wor = (const float*)d_in[11];
    const float* bor = (const float*)d_in[12];
    const float* Woa = (const float*)d_in[13];
    const float* boa = (const float*)d_in[14];
    const float* Wsr = (const float*)d_in[15];
    const float* bsr = (const float*)d_in[16];
    const float* Wsa = (const float*)d_in[17];
    const float* bsa = (const float*)d_in[18];
    const float* Wdr = (const float*)d_in[19];
    const float* bdr = (const float*)d_in[20];
    const float* Wda = (const float*)d_in[21];
    const float* bda = (const float*)d_in[22];
    float* out = (float*)d_out;

    float *Qp, *Kp, *VRp, *VAp, *AGGRp, *AGGAp, *CRp, *CAp;
    cudaGetSymbolAddress((void**)&Qp, g_Q);
    cudaGetSymbolAddress((void**)&Kp, g_K);
    cudaGetSymbolAddress((void**)&VRp, g_VR);
    cudaGetSymbolAddress((void**)&VAp, g_VA);
    cudaGetSymbolAddress((void**)&AGGRp, g_AGGR);
    cudaGetSymbolAddress((void**)&AGGAp, g_AGGA);
    cudaGetSymbolAddress((void**)&CRp, g_CR);
    cudaGetSymbolAddress((void**)&CAp, g_CA);

    cudaMemsetAsync(AGGAp, 0, (size_t)N_ATAC * HID * sizeof(float));

    // input projections
    GemmBatch b1 = {};
    b1.op[0] = {x_rna, Wq, bq, Qp, N_RNA, IN_C, 128, 0};
    b1.op[1] = {x_atac, Wk, bk, Kp, N_ATAC, IN_C, 128, 0};
    b1.op[2] = {x_rna, Wvr, bvr, VRp, N_RNA, IN_C, 128, 0};
    b1.op[3] = {x_atac, Wva, bva, VAp, N_ATAC, IN_C, 128, 0};
    b1.op[4] = {x_rna, Wsr, bsr, CRp, N_RNA, IN_C, 256, 128};
    b1.op[5] = {x_atac, Wsa, bsa, CAp, N_ATAC, IN_C, 256, 128};
    gemm_kernel<<<dim3(128, 6), 256>>>(b1);

    // K -> KT
    transpose_k<<<N_ATAC / 64, 256>>>();

    // masked logits GEMM + group-of-4 maxes (round-10 proven)
    cudaFuncSetAttribute(logits_kernel, cudaFuncAttributeMaxDynamicSharedMemorySize, 68608);
    logits_kernel<<<dim3(N_ATAC / 128, N_RNA / 128, 2), 256, 68608>>>(chrom_mask);

    // LM -> LM2 (max-over-32)
    reduce_lm<<<2 * N_RNA * (N_ATAC / 32) / 256, 256>>>();

    // threshold-gated exact top-10 + weights (round-11 proven)
    scan_kernel<<<2 * N_RNA / 8, 256>>>();

    // sparse aggregation
    agg_kernel<<<2 * N_RNA / 4, 256>>>();

    // out-projections into concat halves
    GemmBatch b2 = {};
    b2.op[0] = {AGGRp, Wor, bor, CRp, N_RNA, HID, 256, 0};
    b2.op[1] = {AGGAp, Woa, boa, CAp, N_ATAC, HID, 256, 0};
    gemm_kernel<<<dim3(128, 2), 256>>>(b2);

    // dim-reduction GEMMs into d_out
    GemmBatch b3 = {};
    b3.op[0] = {CRp, Wdr, bdr, out, N_RNA, 2 * HID, 128, 0};
    b3.op[1] = {CAp, Wda, bda, out + (size_t)N_RNA * HID, N_ATAC, 2 * HID, 128, 0};
    gemm_kernel<<<dim3(128, 2), 256>>>(b3);
}

// round 13
// speedup vs baseline: 4.1466x; 4.1466x over previous
#include <cuda_runtime.h>
#include <math.h>
#include <stdint.h>

#define N_RNA 4096
#define N_ATAC 8192
#define IN_C 256
#define HID 128
#define THR_S 0.8f

// ---------------- scratch (static device memory; no allocations) ----------------
__device__ float g_Q[N_RNA * HID];
__device__ float g_K[N_ATAC * HID];
__device__ float g_KT[HID * N_ATAC];          // K transposed: [d 128][a 8192]
__device__ float g_VR[N_RNA * HID];
__device__ float g_VA[N_ATAC * HID];
__device__ float g_AGGR[N_RNA * HID];
__device__ float g_AGGA[N_ATAC * HID];
__device__ float g_CR[N_RNA * 2 * HID];
__device__ float g_CA[N_ATAC * 2 * HID];
__device__ float g_L[2u * N_RNA * N_ATAC];    // masked logits [h][r][a]  (268 MB)
__device__ float g_LM[2u * N_RNA * (N_ATAC / 4)];  // group-of-4 maxes (67 MB)
__device__ float g_W[2 * N_RNA * 10];         // top-k weights per (h,r)
__device__ int g_WI[2 * N_RNA * 10];          // top-k indices per (h,r)

// ---------------- batched GEMM (unchanged, known-good) ----------------
struct GemmOp {
    const float* A;
    const float* W;
    const float* B;
    float* C;
    int M;
    int K;
    int ldc;
    int coff;
};
struct GemmBatch { GemmOp op[6]; };

__global__ void __launch_bounds__(256) gemm_kernel(GemmBatch batch) {
    const GemmOp op = batch.op[blockIdx.y];
    const int m0 = blockIdx.x * 64;
    if (m0 >= op.M) return;

    __shared__ float a_s[64][33];
    __shared__ float w_s[32][128];

    float acc[8][4];
#pragma unroll
    for (int i = 0; i < 8; ++i) {
        acc[i][0] = 0.f; acc[i][1] = 0.f; acc[i][2] = 0.f; acc[i][3] = 0.f;
    }

    const int t = threadIdx.x;
    const float4* A4 = (const float4*)op.A;
    const float4* W4 = (const float4*)op.W;
    const int Kd4 = op.K >> 2;

    for (int kk = 0; kk < op.K; kk += 32) {
        __syncthreads();
        {
            int k4 = t & 7, r = t >> 3;
#pragma unroll
            for (int rr = 0; rr < 2; ++rr) {
                float4 v = A4[(size_t)(m0 + r + rr * 32) * Kd4 + (kk >> 2) + k4];
                a_s[r + rr * 32][k4 * 4 + 0] = v.x;
                a_s[r + rr * 32][k4 * 4 + 1] = v.y;
                a_s[r + rr * 32][k4 * 4 + 2] = v.z;
                a_s[r + rr * 32][k4 * 4 + 3] = v.w;
            }
        }
        {
#pragma unroll
            for (int p = 0; p < 4; ++p) {
                int idx = t + p * 256;
                int k = idx >> 5, c4 = idx & 31;
                *(float4*)&w_s[k][c4 * 4] = W4[(size_t)(kk + k) * 32 + c4];
            }
        }
        __syncthreads();
#pragma unroll
        for (int k = 0; k < 32; ++k) {
            float4 w4 = *(const float4*)&w_s[k][(t & 31) * 4];
#pragma unroll
            for (int i = 0; i < 8; ++i) {
                float av = a_s[(t >> 5) * 8 + i][k];
                acc[i][0] += av * w4.x;
                acc[i][1] += av * w4.y;
                acc[i][2] += av * w4.z;
                acc[i][3] += av * w4.w;
            }
        }
    }

    const int c = (t & 31) * 4;
    const int rb = (t >> 5) * 8;
    float4 b4 = *(const float4*)&op.B[c];
#pragma unroll
    for (int i = 0; i < 8; ++i) {
        size_t row = (size_t)(m0 + rb + i);
        float4 o;
        o.x = acc[i][0] + b4.x;
        o.y = acc[i][1] + b4.y;
        o.z = acc[i][2] + b4.z;
        o.w = acc[i][3] + b4.w;
        *(float4*)&op.C[row * op.ldc + op.coff + c] = o;
    }
}

// ---------------- K transpose: g_K[a][d] -> g_KT[d][a] ----------------
__global__ void __launch_bounds__(256) transpose_k() {
    __shared__ float ts[64][133];
    const int t = threadIdx.x;
    const int a0 = blockIdx.x * 64;
    const float4* K4 = (const float4*)g_K;
#pragma unroll
    for (int j = 0; j < 8; ++j) {
        int idx = t + 256 * j;
        int r = idx >> 5, c4 = idx & 31;
        float4 v = K4[(size_t)(a0 + r) * 32 + c4];
        ts[r][c4 * 4 + 0] = v.x;
        ts[r][c4 * 4 + 1] = v.y;
        ts[r][c4 * 4 + 2] = v.z;
        ts[r][c4 * 4 + 3] = v.w;
    }
    __syncthreads();
    float4* KT4 = (float4*)g_KT;
#pragma unroll
    for (int j = 0; j < 8; ++j) {
        int idx = t + 256 * j;
        int d = idx >> 4, ac4 = idx & 15;
        float4 o;
        o.x = ts[ac4 * 4 + 0][d];
        o.y = ts[ac4 * 4 + 1][d];
        o.z = ts[ac4 * 4 + 2][d];
        o.w = ts[ac4 * 4 + 3][d];
        KT4[((size_t)d * N_ATAC + a0) / 4 + ac4] = o;
    }
}

// ---------------- logits GEMM (conflict-free) + group-max emission ----------------
__global__ void __launch_bounds__(256, 2) logits_kernel(const float* __restrict__ mask) {
    extern __shared__ float sm[];
    float* const a_f = sm;                          // [128][68] floats
    float4* const b4_s = (float4*)(sm + 128 * 68);  // [64][33] float4

    const int t = threadIdx.x;
    const int n0 = blockIdx.x * 128;
    const int m0 = blockIdx.y * 128;
    const int h = blockIdx.z;

    {
        const float4* Q4 = (const float4*)g_Q;
        float4* a4 = (float4*)a_f;
        const int k4 = t & 15, mq = t >> 4;
#pragma unroll
        for (int j = 0; j < 8; ++j) {
            int mm = mq + 16 * j;
            a4[mm * 17 + k4] = Q4[(size_t)(m0 + mm) * 32 + h * 16 + k4];
        }
    }
    {
        const float4* KT4 = (const float4*)g_KT;
        const int gq = t & 31, k2 = t >> 5;
#pragma unroll
        for (int j = 0; j < 8; ++j) {
            int k = k2 + 8 * j;
            b4_s[k * 33 + gq] =
                KT4[((size_t)(h * 64 + k) * N_ATAC + n0) / 4 + gq];
        }
    }
    __syncthreads();

    const int tx = t & 31;
    const int ty = t >> 5;

    float acc[16][4];
#pragma unroll
    for (int i = 0; i < 16; ++i) {
        acc[i][0] = 0.f; acc[i][1] = 0.f; acc[i][2] = 0.f; acc[i][3] = 0.f;
    }

    const float* arow = a_f + ty * 16 * 68;

#pragma unroll 4
    for (int k = 0; k < 64; ++k) {
        float4 b = b4_s[k * 33 + tx];
#pragma unroll
        for (int i = 0; i < 16; ++i) {
            float av = arow[i * 68 + k];
            acc[i][0] += av * b.x;
            acc[i][1] += av * b.y;
            acc[i][2] += av * b.z;
            acc[i][3] += av * b.w;
        }
    }

    const float4* M4 = (const float4*)mask;
    float4* L4 = (float4*)g_L;
#pragma unroll
    for (int i = 0; i < 16; ++i) {
        const int r = m0 + ty * 16 + i;
        float4 mv = M4[(size_t)r * (N_ATAC / 4) + (n0 >> 2) + tx];
        float4 o;
        o.x = acc[i][0] * mv.x;
        o.y = acc[i][1] * mv.y;
        o.z = acc[i][2] * mv.z;
        o.w = acc[i][3] * mv.w;
        L4[((size_t)h * N_RNA + r) * (N_ATAC / 4) + (n0 >> 2) + tx] = o;
        // group-of-4 max for the scan pre-filter
        g_LM[((size_t)h * N_RNA + r) * (N_ATAC / 4) + (n0 >> 2) + tx] =
            fmaxf(fmaxf(o.x, o.y), fmaxf(o.z, o.w));
    }
}

// ---------------- top-k helpers ----------------
__device__ __forceinline__ bool tk_better(float v, int i, float v2, int i2) {
    return (v > v2) || (v == v2 && i < i2);
}

__device__ __forceinline__ void tk_insert(float* bv, int* bi, float v, int gi) {
    bool done = false;
#pragma unroll
    for (int k = 9; k > 0; --k) {
        if (!done) {
            if (tk_better(v, gi, bv[k - 1], bi[k - 1])) {
                bv[k] = bv[k - 1];
                bi[k] = bi[k - 1];
            } else {
                bv[k] = v;
                bi[k] = gi;
                done = true;
            }
        }
    }
    if (!done) { bv[0] = v; bi[0] = gi; }
}

__device__ __forceinline__ float warp_max(float v) {
#pragma unroll
    for (int off = 16; off; off >>= 1)
        v = fmaxf(v, __shfl_xor_sync(0xffffffffu, v, off));
    return v;
}

// ---------------- scan kernel v2: threshold-gated sparse top-10 ----------------
// Warp per (h,r) row. Seed a SAFE threshold (10th largest of 32 lane-maxes of
// group-maxes: >=10 distinct lanes witness an element >= thr, so the true row
// 10th >= thr and a '>=' filter can never drop a top-10 member). Then scan the
// LM array and touch g_L only for groups whose max passes.
__global__ void __launch_bounds__(256) scan_kernel() {
    __shared__ float tvs[8][32][10];
    __shared__ int tis[8][32][10];

    const int t = threadIdx.x;
    const int w = t >> 5;
    const int lane = t & 31;
    const int ridx = blockIdx.x * 8 + w;           // h*4096 + r

    const float4* LM4 = (const float4*)g_LM;
    const float4* L4 = (const float4*)g_L;
    const size_t mbase = (size_t)ridx * (N_ATAC / 16);  // 512 float4 of maxes
    const size_t lbase = (size_t)ridx * (N_ATAC / 4);   // 2048 float4 of logits

    // ---- pass A: lane max over this lane's 16 LM float4s (no inserts) ----
    float lmax = -1e30f;
#pragma unroll 4
    for (int j = 0; j < 16; ++j) {
        float4 v = LM4[mbase + j * 32 + lane];
        lmax = fmaxf(lmax, fmaxf(fmaxf(v.x, v.y), fmaxf(v.z, v.w)));
    }

    // ---- warp-select 10th largest of the 32 lane maxes -> safe thr ----
    float x = lmax;
    float thr = -1e30f;
#pragma unroll
    for (int k = 0; k < 10; ++k) {
        float m = warp_max(x);
        thr = m;
        unsigned b = __ballot_sync(0xffffffffu, x == m);
        int src = __ffs(b) - 1;
        if (lane == src) x = -1e30f;
    }

    // ---- main pass: gated exact top-10 ----
    float bv[10];
    int bi[10];
#pragma unroll
    for (int k = 0; k < 10; ++k) { bv[k] = -1e30f; bi[k] = 0x7fffffff; }

    for (int j = 0; j < 16; ++j) {
        float4 mv = LM4[mbase + j * 32 + lane];
        float thr_eff = fmaxf(thr, bv[9]);
        float mx = fmaxf(fmaxf(mv.x, mv.y), fmaxf(mv.z, mv.w));
        if (mx >= thr_eff) {
            const int gq = j * 32 + lane;          // float4-of-groups index
            float gm[4] = {mv.x, mv.y, mv.z, mv.w};
#pragma unroll
            for (int gg = 0; gg < 4; ++gg) {
                if (gm[gg] >= fmaxf(thr, bv[9])) {
                    const int grp = gq * 4 + gg;   // group of 4 elements
                    float4 lv = L4[lbase + grp];
                    const int a0 = grp * 4;
                    if (tk_better(lv.x, a0, bv[9], bi[9])) tk_insert(bv, bi, lv.x, a0);
                    if (tk_better(lv.y, a0 + 1, bv[9], bi[9])) tk_insert(bv, bi, lv.y, a0 + 1);
                    if (tk_better(lv.z, a0 + 2, bv[9], bi[9])) tk_insert(bv, bi, lv.z, a0 + 2);
                    if (tk_better(lv.w, a0 + 3, bv[9], bi[9])) tk_insert(bv, bi, lv.w, a0 + 3);
                }
            }
        }
        if ((j & 3) == 3) thr = fmaxf(thr, warp_max(bv[9]));  // safe tighten
    }

#pragma unroll
    for (int k = 0; k < 10; ++k) { tvs[w][lane][k] = bv[k]; tis[w][lane][k] = bi[k]; }
    __syncwarp();

    if (lane < 8) {
        float fv[10];
        int fi[10];
#pragma unroll
        for (int k = 0; k < 10; ++k) { fv[k] = -1e30f; fi[k] = 0x7fffffff; }
        for (int s = 0; s < 4; ++s)
            for (int k = 0; k < 10; ++k) {
                float v = tvs[w][lane * 4 + s][k];
                int gi = tis[w][lane * 4 + s][k];
                if (tk_better(v, gi, fv[9], fi[9])) tk_insert(fv, fi, v, gi);
            }
#pragma unroll
        for (int k = 0; k < 10; ++k) { tvs[w][lane][k] = fv[k]; tis[w][lane][k] = fi[k]; }
    }
    __syncwarp();

    if (lane == 0) {
        float fv[10];
        int fi[10];
#pragma unroll
        for (int k = 0; k < 10; ++k) { fv[k] = -1e30f; fi[k] = 0x7fffffff; }
        for (int s = 0; s < 8; ++s)
            for (int k = 0; k < 10; ++k) {
                float v = tvs[w][s][k];
                int gi = tis[w][s][k];
                if (tk_better(v, gi, fv[9], fi[9])) tk_insert(fv, fi, v, gi);
            }
        float sig[10];
#pragma unroll
        for (int k = 0; k < 10; ++k) sig[k] = 1.f / (1.f + expf(-fv[k]));
        float e[10];
        float den = 0.f;
#pragma unroll
        for (int k = 0; k < 10; ++k) { e[k] = expf(sig[k] - sig[0]); den += e[k]; }
        float inv = 1.f / den;
#pragma unroll
        for (int k = 0; k < 10; ++k) {
            float ww = e[k] * inv;
            if (!(sig[k] > THR_S)) ww = 0.f;
            g_W[ridx * 10 + k] = ww;
            g_WI[ridx * 10 + k] = fi[k];
        }
    }
}

// ---------------- aggregation kernel: sparse gather + scatter ----------------
__global__ void __launch_bounds__(256) agg_kernel() {
    const int t = threadIdx.x;
    const int d = t & 63;
    const int q = t >> 6;
    const int ridx = blockIdx.x * 4 + q;
    const int h = ridx >> 12;
    const int r = ridx & 4095;

    float wv[10];
    int wi[10];
#pragma unroll
    for (int k = 0; k < 10; ++k) { wv[k] = g_W[ridx * 10 + k]; wi[k] = g_WI[ridx * 10 + k]; }

    const float vr = g_VR[(size_t)r * 128 + h * 64 + d];
    float accO = 0.f;
#pragma unroll
    for (int k = 0; k < 10; ++k) {
        float w = wv[k];
        int a = wi[k];
        if (w != 0.f) {
            accO += w * g_VA[(size_t)a * 128 + h * 64 + d];
            atomicAdd(&g_AGGA[(size_t)a * 128 + h * 64 + d], w * vr);
        }
    }
    g_AGGR[(size_t)r * 128 + h * 64 + d] = accO;
}

// ---------------- launch ----------------
extern "C" void kernel_launch(void* const* d_in, const int* in_sizes, int n_in,
                              void* d_out, int out_size) {
    const float* x_rna = (const float*)d_in[0];
    const float* x_atac = (const float*)d_in[1];
    const float* chrom_mask = (const float*)d_in[2];
    const float* Wq = (const float*)d_in[3];
    const float* bq = (const float*)d_in[4];
    const float* Wk = (const float*)d_in[5];
    const float* bk = (const float*)d_in[6];
    const float* Wvr = (const float*)d_in[7];
    const float* bvr = (const float*)d_in[8];
    const float* Wva = (const float*)d_in[9];
    const float* bva = (const float*)d_in[10];
    const float* Wor = (const float*)d_in[11];
    const float* bor = (const float*)d_in[12];
    const float* Woa = (const float*)d_in[13];
    const float* boa = (const float*)d_in[14];
    const float* Wsr = (const float*)d_in[15];
    const float* bsr = (const float*)d_in[16];
    const float* Wsa = (const float*)d_in[17];
    const float* bsa = (const float*)d_in[18];
    const float* Wdr = (const float*)d_in[19];
    const float* bdr = (const float*)d_in[20];
    const float* Wda = (const float*)d_in[21];
    const float* bda = (const float*)d_in[22];
    float* out = (float*)d_out;

    float *Qp, *Kp, *VRp, *VAp, *AGGRp, *AGGAp, *CRp, *CAp;
    cudaGetSymbolAddress((void**)&Qp, g_Q);
    cudaGetSymbolAddress((void**)&Kp, g_K);
    cudaGetSymbolAddress((void**)&VRp, g_VR);
    cudaGetSymbolAddress((void**)&VAp, g_VA);
    cudaGetSymbolAddress((void**)&AGGRp, g_AGGR);
    cudaGetSymbolAddress((void**)&AGGAp, g_AGGA);
    cudaGetSymbolAddress((void**)&CRp, g_CR);
    cudaGetSymbolAddress((void**)&CAp, g_CA);

    cudaMemsetAsync(AGGAp, 0, (size_t)N_ATAC * HID * sizeof(float));

    // input projections
    GemmBatch b1 = {};
    b1.op[0] = {x_rna, Wq, bq, Qp, N_RNA, IN_C, 128, 0};
    b1.op[1] = {x_atac, Wk, bk, Kp, N_ATAC, IN_C, 128, 0};
    b1.op[2] = {x_rna, Wvr, bvr, VRp, N_RNA, IN_C, 128, 0};
    b1.op[3] = {x_atac, Wva, bva, VAp, N_ATAC, IN_C, 128, 0};
    b1.op[4] = {x_rna, Wsr, bsr, CRp, N_RNA, IN_C, 256, 128};
    b1.op[5] = {x_atac, Wsa, bsa, CAp, N_ATAC, IN_C, 256, 128};
    gemm_kernel<<<dim3(128, 6), 256>>>(b1);

    // K -> KT
    transpose_k<<<N_ATAC / 64, 256>>>();

    // masked logits GEMM + group maxes
    cudaFuncSetAttribute(logits_kernel, cudaFuncAttributeMaxDynamicSharedMemorySize, 68608);
    logits_kernel<<<dim3(N_ATAC / 128, N_RNA / 128, 2), 256, 68608>>>(chrom_mask);

    // threshold-gated exact top-10 + weights
    scan_kernel<<<2 * N_RNA / 8, 256>>>();

    // sparse aggregation
    agg_kernel<<<2 * N_RNA / 4, 256>>>();

    // out-projections into concat halves
    GemmBatch b2 = {};
    b2.op[0] = {AGGRp, Wor, bor, CRp, N_RNA, HID, 256, 0};
    b2.op[1] = {AGGAp, Woa, boa, CAp, N_ATAC, HID, 256, 0};
    gemm_kernel<<<dim3(128, 2), 256>>>(b2);

    // dim-reduction GEMMs into d_out
    GemmBatch b3 = {};
    b3.op[0] = {CRp, Wdr, bdr, out, N_RNA, 2 * HID, 128, 0};
    b3.op[1] = {CAp, Wda, bda, out + (size_t)N_RNA * HID, N_ATAC, 2 * HID, 128, 0};
    gemm_kernel<<<dim3(128, 2), 256>>>(b3);
}